// round 1
// baseline (speedup 1.0000x reference)
#include <cuda_runtime.h>
#include <cuda_bf16.h>
#include <cstdint>

// BitConv2dInferP2: 3x3 ternary conv, power-of-two scales, int8 activation grid.
// Strategy R1: exact integer conv via dp4a.
//   x (fp32) -> quantize/pack int8x4 [n][Cin/4][h][w]  (25.7MB device scratch, L2-resident)
//   w (ternary) -> packed int8x4 [c4*9+tap][co]        (36KB, staged to smem per block)
//   conv: 1 thread = 1 pixel, all 64 Cout accumulators in registers, dp4a core.
//   epilogue: y = acc * 2^(act_exp+s_exp[co]) + bias[co]   (exact)

#define N_    32
#define CIN   64
#define H_    112
#define W_    112
#define COUT  64
#define C4    16            // CIN/4
#define HW    (H_*W_)
#define NPIX  (N_*HW)

__device__ int  g_is_i32;                       // 1 if int8 inputs were materialized as int32
__device__ int4 g_wpack4[C4*9*COUT/4];          // [(c4*9+tap)*64 + co], 4 co per int4
__device__ int  g_x8[N_*C4*HW];                 // packed activations, [n][c4][h][w]

// Load a logically-int8 value from a buffer that may be int8 or int32 backed.
__device__ __forceinline__ int load_q(const void* p, int i, int is32) {
    if (is32) return ((const int*)p)[i];
    return (int)(((const signed char*)p)[i]);
}

// ---------------------------------------------------------------------------
// K0: dtype detection. If w_q is int32-backed, its first words are all in
// {-1,0,1}. If int8-backed, words are packs of ternary bytes and land outside
// that set with overwhelming probability. Deterministic given fixed inputs.
// ---------------------------------------------------------------------------
__global__ void detect_kernel(const int* __restrict__ wq_words) {
    bool all_small = true;
    #pragma unroll
    for (int i = 0; i < 64; ++i) {
        int v = wq_words[i];
        if (v < -1 || v > 1) all_small = false;
    }
    g_is_i32 = all_small ? 1 : 0;
}

// ---------------------------------------------------------------------------
// K1: pack weights. w_q[co][ci][kh][kw] -> word[(c4*9+tap)*64+co] with 4
// consecutive input channels per byte lane (matches activation packing).
// ---------------------------------------------------------------------------
__global__ void pack_w_kernel(const void* __restrict__ wq) {
    int i = blockIdx.x*blockDim.x + threadIdx.x;
    if (i >= C4*9*COUT) return;
    int is32 = g_is_i32;
    int co  = i & 63;
    int r   = i >> 6;          // c4*9 + tap
    int tap = r % 9;
    int c4  = r / 9;
    int word = 0;
    #pragma unroll
    for (int b = 0; b < 4; ++b) {
        int ci = c4*4 + b;
        int v = load_q(wq, (co*CIN + ci)*9 + tap, is32);
        word |= (v & 0xFF) << (8*b);
    }
    ((int*)g_wpack4)[i] = word;
}

// ---------------------------------------------------------------------------
// K2: quantize + pack activations. Replays the reference's fake-quant:
// clip(x,±1), round-half-even (rintf) of x/2^act_exp, clip ±127.
// Output layout [n][c4][h][w] so conv reads one int32 per 4 channels.
// ---------------------------------------------------------------------------
__global__ void quant_kernel(const float* __restrict__ x,
                             const void* __restrict__ act_exp_raw) {
    int i = blockIdx.x*blockDim.x + threadIdx.x;
    if (i >= N_*C4*HW) return;
    float inv_step = exp2f(-(float)load_q(act_exp_raw, 0, g_is_i32));
    int pix = i % HW;
    int t   = i / HW;                         // n*16 + c4
    const float* xp = x + (t*4)*HW + pix;     // channel base = n*64 + c4*4 = t*4
    int word = 0;
    #pragma unroll
    for (int b = 0; b < 4; ++b) {
        float v = xp[b*HW];
        v = fminf(fmaxf(v, -1.f), 1.f);
        float r = rintf(v * inv_step);        // RN = half-to-even, matches jnp.round
        r = fminf(fmaxf(r, -127.f), 127.f);
        word |= (((int)r) & 0xFF) << (8*b);
    }
    g_x8[i] = word;
}

// ---------------------------------------------------------------------------
// K3: conv core. One thread computes one (n,h,w) pixel for all 64 Cout.
// Weights staged to smem as int4 (one LDS.128 broadcast feeds 4 dp4a).
// Per (tap,c4): 1 LDG + 16 LDS.128 + 64 DP4A.
// ---------------------------------------------------------------------------
__global__ void __launch_bounds__(256)
conv_kernel(const float* __restrict__ bias,
            const void*  __restrict__ s_exp_raw,
            const void*  __restrict__ act_exp_raw,
            float*       __restrict__ out) {
    __shared__ int4  wsm[C4*9*16];            // 36,864 B
    __shared__ float sh_scale[COUT];
    __shared__ float sh_bias[COUT];

    for (int i = threadIdx.x; i < C4*9*16; i += blockDim.x)
        wsm[i] = g_wpack4[i];
    if (threadIdx.x < COUT) {
        int is32 = g_is_i32;
        int ae = load_q(act_exp_raw, 0, is32);
        int se = load_q(s_exp_raw, threadIdx.x, is32);
        sh_scale[threadIdx.x] = exp2f((float)(ae + se));   // exact power of two
        sh_bias[threadIdx.x]  = bias[threadIdx.x];
    }
    __syncthreads();

    int p = blockIdx.x*blockDim.x + threadIdx.x;
    if (p >= NPIX) return;
    int w = p % W_;
    int t = p / W_;
    int h = t % H_;
    int n = t / H_;

    int acc[COUT];
    #pragma unroll
    for (int c = 0; c < COUT; ++c) acc[c] = 0;

    const int* __restrict__ xb = g_x8 + n*(C4*HW);

    for (int tap = 0; tap < 9; ++tap) {
        int hh = h + tap/3 - 1;
        int ww = w + tap%3 - 1;
        if ((unsigned)hh >= (unsigned)H_ || (unsigned)ww >= (unsigned)W_) continue;
        const int* __restrict__ xp = xb + hh*W_ + ww;
        #pragma unroll 2
        for (int c4 = 0; c4 < C4; ++c4) {
            int xv = __ldg(xp + c4*HW);
            const int4* wr = &wsm[(c4*9 + tap)*16];
            #pragma unroll
            for (int q = 0; q < 16; ++q) {
                int4 wv = wr[q];
                acc[4*q+0] = __dp4a(xv, wv.x, acc[4*q+0]);
                acc[4*q+1] = __dp4a(xv, wv.y, acc[4*q+1]);
                acc[4*q+2] = __dp4a(xv, wv.z, acc[4*q+2]);
                acc[4*q+3] = __dp4a(xv, wv.w, acc[4*q+3]);
            }
        }
    }

    float* __restrict__ op = out + (n*COUT*HW) + h*W_ + w;
    #pragma unroll
    for (int c = 0; c < COUT; ++c)
        op[c*HW] = (float)acc[c] * sh_scale[c] + sh_bias[c];
}

// ---------------------------------------------------------------------------
// kernel_launch: 4 graph-capturable launches on the capture stream.
// Inputs (metadata order = setup_inputs order):
//   d_in[0] x        float32 [32,64,112,112]
//   d_in[1] w_q      int8    [64,64,3,3]     (dtype hedged via detect_kernel)
//   d_in[2] s_exp    int8    [64,1,1]
//   d_in[3] bias     float32 [64]
//   d_in[4] act_exp  int8    scalar
// Output: float32 [32,64,112,112]
// ---------------------------------------------------------------------------
extern "C" void kernel_launch(void* const* d_in, const int* in_sizes, int n_in,
                              void* d_out, int out_size) {
    (void)in_sizes; (void)n_in; (void)out_size;
    const float* x    = (const float*)d_in[0];
    const void*  wq   = d_in[1];
    const void*  sexp = d_in[2];
    const float* bias = (const float*)d_in[3];
    const void*  aexp = d_in[4];
    float* out = (float*)d_out;

    detect_kernel<<<1, 1>>>((const int*)wq);
    pack_w_kernel<<<(C4*9*COUT + 255)/256, 256>>>(wq);
    quant_kernel<<<(N_*C4*HW + 255)/256, 256>>>(x, aexp);
    conv_kernel<<<(NPIX + 255)/256, 256>>>(bias, sexp, aexp, out);
}

// round 12
// speedup vs baseline: 1.0892x; 1.0892x over previous
#include <cuda_runtime.h>
#include <cuda_bf16.h>
#include <cstdint>

// BitConv2dInferP2 — R12 (identical to R2..R11; broker timeouts, never run):
// per-tap implicit GEMM on tensor cores (mma.sync m16n8k32 s8).
//   x (fp32) -> quantize/pack int8x4  g_x8[n][c4][h][w]   (L2-resident scratch)
//   w ternary -> packed into mma B-fragment order          g_wfrag (36KB, L1-resident)
//   conv: block = 256 pixels x 64 Cout; per tap stage shifted activations into
//         smem, then m16n8k32 s8 IMMA; exact s32 accumulation.
//   epilogue: y = acc * 2^(act_exp+s_exp[co]) + bias[co]   (exact, rel_err 0)

#define N_    32
#define CIN   64
#define H_    112
#define W_    112
#define COUT  64
#define C4    16
#define HW    (H_*W_)
#define NPIX  (N_*HW)          // 401408 = 256 * 1568
#define MTILE 256

__device__ int g_is_i32;                 // int8 inputs materialized as int32?
__device__ int g_wfrag[18*8*8*8];        // [ts=tap*2+s][nf][j][w] B-fragment words
__device__ int g_x8[N_*C4*HW];           // packed activations [n][c4][h][w]

__device__ __forceinline__ int load_q(const void* p, int i, int is32) {
    if (is32) return ((const int*)p)[i];
    return (int)(((const signed char*)p)[i]);
}

// ---------------------------------------------------------------------------
// K0: dtype detection (int8 vs int32 backing for the quantized inputs).
// ---------------------------------------------------------------------------
__global__ void detect_kernel(const int* __restrict__ wq_words) {
    bool all_small = true;
    #pragma unroll
    for (int i = 0; i < 64; ++i) {
        int v = wq_words[i];
        if (v < -1 || v > 1) all_small = false;
    }
    g_is_i32 = all_small ? 1 : 0;
}

// ---------------------------------------------------------------------------
// K1: pack weights into mma.sync m16n8k32 B-fragment order.
// B operand (col-major 32x8): lane: j = lane>>2 (col), tig = lane&3,
//   b0 = k-bytes 4*tig..4*tig+3, b1 = k-bytes 16+4*tig..+3.
// Stored per (ts = tap*2 + kstep): word[nf][j][w], w=0..7, where word w packs
// ci = kstep*32 + 4w + b (byte lanes b=0..3), col co = nf*8 + j.
// ---------------------------------------------------------------------------
__global__ void pack_w_kernel(const void* __restrict__ wq) {
    int i = blockIdx.x*blockDim.x + threadIdx.x;
    if (i >= 18*8*8*8) return;
    int is32 = g_is_i32;
    int w   = i & 7;
    int j   = (i >> 3) & 7;
    int nf  = (i >> 6) & 7;
    int ts  = i >> 9;          // 0..17
    int tap = ts >> 1;
    int s   = ts & 1;
    int co  = nf*8 + j;
    int word = 0;
    #pragma unroll
    for (int b = 0; b < 4; ++b) {
        int ci = s*32 + w*4 + b;
        int v = load_q(wq, (co*CIN + ci)*9 + tap, is32);
        word |= (v & 0xFF) << (8*b);
    }
    g_wfrag[i] = word;
}

// ---------------------------------------------------------------------------
// K2: fake-quant replay + pack 4 channels/word. Layout [n][c4][h][w].
// ---------------------------------------------------------------------------
__global__ void quant_kernel(const float* __restrict__ x,
                             const void* __restrict__ act_exp_raw) {
    int i = blockIdx.x*blockDim.x + threadIdx.x;
    if (i >= N_*C4*HW) return;
    float inv_step = exp2f(-(float)load_q(act_exp_raw, 0, g_is_i32));
    int pix = i % HW;
    int t   = i / HW;                     // n*16 + c4
    const float* xp = x + (t*4)*HW + pix;
    int word = 0;
    #pragma unroll
    for (int b = 0; b < 4; ++b) {
        float v = xp[b*HW];
        v = fminf(fmaxf(v, -1.f), 1.f);
        float r = rintf(v * inv_step);    // RN half-to-even, matches jnp.round
        r = fminf(fmaxf(r, -127.f), 127.f);
        word |= (((int)r) & 0xFF) << (8*b);
    }
    g_x8[i] = word;
}

// ---------------------------------------------------------------------------
// K3: conv core — implicit GEMM, one 256-pixel x 64-Cout tile per block.
// 8 warps; warp owns M-frags {warp*32, warp*32+16} x all 8 N-frags.
// Per tap: stage shifted+masked activations to smem (pitch 17 words,
// conflict-free STS), then 2 ksteps x 8 nf x 2 mf mma.sync m16n8k32.
// ---------------------------------------------------------------------------
__global__ void __launch_bounds__(256)
conv_kernel(const float* __restrict__ bias,
            const void*  __restrict__ s_exp_raw,
            const void*  __restrict__ act_exp_raw,
            float*       __restrict__ out) {
    __shared__ int   sA[MTILE*17];        // 17408 B
    __shared__ float sh_scale[COUT];
    __shared__ float sh_bias[COUT];

    int tid = threadIdx.x;
    if (tid < COUT) {
        int is32 = g_is_i32;
        int ae = load_q(act_exp_raw, 0, is32);
        int se = load_q(s_exp_raw, tid, is32);
        sh_scale[tid] = exp2f((float)(ae + se));   // exact power of two
        sh_bias[tid]  = bias[tid];
    }

    const int blockPix = blockIdx.x * MTILE;
    const int n  = blockPix / HW;                 // HW % MTILE == 0: n uniform
    const int hw = blockPix - n*HW + tid;         // this thread's staging pixel
    const int w  = hw % W_;
    const int h  = hw / W_;

    const int lane = tid & 31;
    const int warp = tid >> 5;
    const int rt   = lane >> 2;                   // groupID
    const int tig  = lane & 3;

    int acc[2][8][4];
    #pragma unroll
    for (int mf = 0; mf < 2; ++mf)
        #pragma unroll
        for (int nf = 0; nf < 8; ++nf)
            #pragma unroll
            for (int k = 0; k < 4; ++k) acc[mf][nf][k] = 0;

    const int* __restrict__ xbase = g_x8 + n*(C4*HW);

    for (int tap = 0; tap < 9; ++tap) {
        // ---- stage: each thread owns one pixel, loops 16 channel-words ----
        int hh = h + tap/3 - 1;
        int ww = w + tap%3 - 1;
        bool valid = ((unsigned)hh < (unsigned)H_) && ((unsigned)ww < (unsigned)W_);
        const int* __restrict__ src = xbase + hh*W_ + ww;
        #pragma unroll
        for (int c4 = 0; c4 < C4; ++c4)
            sA[tid*17 + c4] = valid ? __ldg(src + c4*HW) : 0;
        __syncthreads();

        // ---- mma phase ----
        #pragma unroll
        for (int s = 0; s < 2; ++s) {
            int a[2][4];
            #pragma unroll
            for (int mf = 0; mf < 2; ++mf) {
                int base = (warp*32 + mf*16 + rt)*17 + s*8 + tig;
                a[mf][0] = sA[base];                // (row,      k 4t..)
                a[mf][1] = sA[base + 8*17];         // (row+8,    k 4t..)
                a[mf][2] = sA[base + 4];            // (row,   16+k 4t..)
                a[mf][3] = sA[base + 8*17 + 4];     // (row+8, 16+k 4t..)
            }
            const int* __restrict__ bw =
                g_wfrag + (tap*2 + s)*512 + (lane >> 2)*8 + (lane & 3);
            #pragma unroll
            for (int nf = 0; nf < 8; ++nf) {
                int b0 = __ldg(bw + nf*64);
                int b1 = __ldg(bw + nf*64 + 4);
                #pragma unroll
                for (int mf = 0; mf < 2; ++mf) {
                    asm volatile(
                        "mma.sync.aligned.m16n8k32.row.col.s32.s8.s8.s32 "
                        "{%0,%1,%2,%3},{%4,%5,%6,%7},{%8,%9},{%0,%1,%2,%3};"
                        : "+r"(acc[mf][nf][0]), "+r"(acc[mf][nf][1]),
                          "+r"(acc[mf][nf][2]), "+r"(acc[mf][nf][3])
                        : "r"(a[mf][0]), "r"(a[mf][1]),
                          "r"(a[mf][2]), "r"(a[mf][3]),
                          "r"(b0), "r"(b1));
                }
            }
        }
        __syncthreads();
    }

    // ---- epilogue: D frag (row = rt/rt+8, col = 2*tig/2*tig+1) ----
    const int hwBase = blockPix - n*HW;
    float* __restrict__ obase = out + (size_t)n*COUT*HW;
    #pragma unroll
    for (int mf = 0; mf < 2; ++mf) {
        int pl = warp*32 + mf*16 + rt;
        #pragma unroll
        for (int nf = 0; nf < 8; ++nf) {
            int co0 = nf*8 + 2*tig;
            #pragma unroll
            for (int k = 0; k < 4; ++k) {
                int co  = co0 + (k & 1);
                int pli = pl + ((k >= 2) ? 8 : 0);
                obase[co*HW + hwBase + pli] =
                    (float)acc[mf][nf][k] * sh_scale[co] + sh_bias[co];
            }
        }
    }
}

// ---------------------------------------------------------------------------
// kernel_launch — 4 graph-capturable launches.
//   d_in[0] x (f32), d_in[1] w_q (i8), d_in[2] s_exp (i8),
//   d_in[3] bias (f32), d_in[4] act_exp (i8).  out: f32 [32,64,112,112].
// ---------------------------------------------------------------------------
extern "C" void kernel_launch(void* const* d_in, const int* in_sizes, int n_in,
                              void* d_out, int out_size) {
    (void)in_sizes; (void)n_in; (void)out_size;
    const float* x    = (const float*)d_in[0];
    const void*  wq   = d_in[1];
    const void*  sexp = d_in[2];
    const float* bias = (const float*)d_in[3];
    const void*  aexp = d_in[4];
    float* out = (float*)d_out;

    detect_kernel<<<1, 1>>>((const int*)wq);
    pack_w_kernel<<<(18*8*8*8 + 255)/256, 256>>>(wq);
    quant_kernel<<<(N_*C4*HW + 255)/256, 256>>>(x, aexp);
    conv_kernel<<<NPIX/MTILE, 256>>>(bias, sexp, aexp, out);
}